// round 1
// baseline (speedup 1.0000x reference)
#include <cuda_runtime.h>
#include <math.h>

// Problem constants
constexpr int B_  = 2;
constexpr int T_  = 2048;
constexpr int C_  = 768;
constexpr int NH_ = 12;
constexpr int HS_ = 64;           // C_/NH_
constexpr int M_  = B_ * T_;      // 4096 rows of x
constexpr int N3_ = 3 * C_;       // 2304 qkv cols
constexpr int K_  = C_;           // 768 reduction

// Scratch for Q/K/V in [B, NH, T, HS] layout (no cudaMalloc allowed)
__device__ float g_q[(size_t)B_ * NH_ * T_ * HS_];
__device__ float g_k[(size_t)B_ * NH_ * T_ * HS_];
__device__ float g_v[(size_t)B_ * NH_ * T_ * HS_];

// ---------------------------------------------------------------------------
// Kernel 1: qkv = x @ w + b, scattered into g_q/g_k/g_v as [B, NH, T, HS]
// 128x128 tile, BK=8, 256 threads, 8x8 register blocking.
// ---------------------------------------------------------------------------
__global__ __launch_bounds__(256) void qkv_gemm_kernel(
    const float* __restrict__ x,      // [M_, K_]
    const float* __restrict__ w,      // [K_, N3_]
    const float* __restrict__ bias)   // [N3_]
{
    __shared__ float As[8][128];      // transposed: As[k][m]
    __shared__ float Bs[8][128];      // Bs[k][n]

    const int tid = threadIdx.x;
    const int m0 = blockIdx.y * 128;
    const int n0 = blockIdx.x * 128;
    const int ty = tid / 16;          // 0..15 -> rows ty*8..+7
    const int tx = tid % 16;          // 0..15 -> cols tx*8..+7

    const int arow = tid >> 1;        // 0..127
    const int acol = (tid & 1) * 4;   // 0 or 4
    const int brow = tid >> 5;        // 0..7
    const int bcol = (tid & 31) * 4;  // 0..124

    float acc[8][8];
#pragma unroll
    for (int i = 0; i < 8; i++)
#pragma unroll
        for (int j = 0; j < 8; j++) acc[i][j] = 0.0f;

    for (int k0 = 0; k0 < K_; k0 += 8) {
        float4 av = *reinterpret_cast<const float4*>(
            &x[(size_t)(m0 + arow) * K_ + k0 + acol]);
        As[acol + 0][arow] = av.x;
        As[acol + 1][arow] = av.y;
        As[acol + 2][arow] = av.z;
        As[acol + 3][arow] = av.w;
        float4 bv = *reinterpret_cast<const float4*>(
            &w[(size_t)(k0 + brow) * N3_ + n0 + bcol]);
        *reinterpret_cast<float4*>(&Bs[brow][bcol]) = bv;
        __syncthreads();

#pragma unroll
        for (int k = 0; k < 8; k++) {
            float af[8], bf[8];
            *reinterpret_cast<float4*>(&af[0]) =
                *reinterpret_cast<const float4*>(&As[k][ty * 8]);
            *reinterpret_cast<float4*>(&af[4]) =
                *reinterpret_cast<const float4*>(&As[k][ty * 8 + 4]);
            *reinterpret_cast<float4*>(&bf[0]) =
                *reinterpret_cast<const float4*>(&Bs[k][tx * 8]);
            *reinterpret_cast<float4*>(&bf[4]) =
                *reinterpret_cast<const float4*>(&Bs[k][tx * 8 + 4]);
#pragma unroll
            for (int i = 0; i < 8; i++)
#pragma unroll
                for (int j = 0; j < 8; j++)
                    acc[i][j] += af[i] * bf[j];
        }
        __syncthreads();
    }

    // Epilogue: add bias, scatter to [B, NH, T, HS] per q/k/v
#pragma unroll
    for (int i = 0; i < 8; i++) {
        const int m = m0 + ty * 8 + i;
        const int bb = m / T_;
        const int t  = m % T_;
#pragma unroll
        for (int j = 0; j < 8; j++) {
            const int n = n0 + tx * 8 + j;
            const float val = acc[i][j] + bias[n];
            const int which = n / C_;          // 0=q 1=k 2=v (constant per tile)
            const int wn    = n - which * C_;
            const int head  = wn / HS_;
            const int d     = wn % HS_;
            float* dst = (which == 0) ? g_q : (which == 1) ? g_k : g_v;
            dst[(((size_t)bb * NH_ + head) * T_ + t) * HS_ + d] = val;
        }
    }
}

// ---------------------------------------------------------------------------
// Kernel 2: flash-style causal attention.
// One CTA per (b, h, 64-row q-tile). 256 threads: thread t -> row r = t/4,
// lane slot seg = t%4. Thread owns keys kl = 4*kk + seg (interleaved) for S,
// and output cols c = 4*i + seg (interleaved) for PV -> all LDS conflict-free.
// ---------------------------------------------------------------------------
constexpr int LDP = 68;  // padded row stride (floats), keeps 16B alignment
constexpr int ATTN_SMEM = 4 * 64 * LDP * (int)sizeof(float);  // 69632 B

__global__ __launch_bounds__(256) void attn_kernel(float* __restrict__ out)
{
    extern __shared__ float sm[];
    float* Qs = sm;                 // [64][LDP]
    float* Ks = Qs + 64 * LDP;
    float* Vs = Ks + 64 * LDP;
    float* Ps = Vs + 64 * LDP;

    const int tid = threadIdx.x;
    const int qt = blockIdx.x;      // q tile (64 rows)
    const int h  = blockIdx.y;
    const int b  = blockIdx.z;
    const size_t base = ((size_t)b * NH_ + h) * T_ * HS_;

    const int r   = tid >> 2;       // 0..63 query row in tile
    const int seg = tid & 3;        // 0..3
    const int qg  = qt * 64 + r;    // global query index

    // Cooperative Q tile load (row = tid/4, 16 contiguous floats per thread)
    {
        const int row = tid >> 2;
        const int cp  = (tid & 3) * 16;
        const float* src = g_q + base + (size_t)(qt * 64 + row) * HS_ + cp;
        float* dst = Qs + row * LDP + cp;
#pragma unroll
        for (int i = 0; i < 4; i++)
            *reinterpret_cast<float4*>(dst + 4 * i) =
                *reinterpret_cast<const float4*>(src + 4 * i);
    }

    float m_i = -INFINITY;
    float l_i = 0.0f;
    float acc[16];
#pragma unroll
    for (int i = 0; i < 16; i++) acc[i] = 0.0f;

    const float scale = 0.125f;  // 1/sqrt(64)

    for (int j = 0; j <= qt; j++) {
        __syncthreads();  // protect K/V from previous iteration readers
        {
            const int row = tid >> 2;
            const int cp  = (tid & 3) * 16;
            const float* ksrc = g_k + base + (size_t)(j * 64 + row) * HS_ + cp;
            const float* vsrc = g_v + base + (size_t)(j * 64 + row) * HS_ + cp;
            float* kd = Ks + row * LDP + cp;
            float* vd = Vs + row * LDP + cp;
#pragma unroll
            for (int i = 0; i < 4; i++) {
                *reinterpret_cast<float4*>(kd + 4 * i) =
                    *reinterpret_cast<const float4*>(ksrc + 4 * i);
                *reinterpret_cast<float4*>(vd + 4 * i) =
                    *reinterpret_cast<const float4*>(vsrc + 4 * i);
            }
        }
        __syncthreads();

        // S = Q K^T for this thread's 16 interleaved keys
        float s[16];
#pragma unroll
        for (int i = 0; i < 16; i++) s[i] = 0.0f;
#pragma unroll
        for (int d = 0; d < 64; d += 4) {
            const float4 qv =
                *reinterpret_cast<const float4*>(Qs + r * LDP + d);
#pragma unroll
            for (int kk = 0; kk < 16; kk++) {
                const float4 kv = *reinterpret_cast<const float4*>(
                    Ks + (4 * kk + seg) * LDP + d);
                s[kk] += qv.x * kv.x + qv.y * kv.y + qv.z * kv.z + qv.w * kv.w;
            }
        }

        // scale + causal mask
#pragma unroll
        for (int kk = 0; kk < 16; kk++) {
            const int kgl = j * 64 + 4 * kk + seg;
            s[kk] = (kgl <= qg) ? s[kk] * scale : -INFINITY;
        }

        // row max (16 local + reduce across quad of 4 lanes)
        float mymax = s[0];
#pragma unroll
        for (int kk = 1; kk < 16; kk++) mymax = fmaxf(mymax, s[kk]);
        mymax = fmaxf(mymax, __shfl_xor_sync(0xffffffffu, mymax, 1));
        mymax = fmaxf(mymax, __shfl_xor_sync(0xffffffffu, mymax, 2));
        const float m_new = fmaxf(m_i, mymax);   // finite: diagonal always valid
        const float corr  = __expf(m_i - m_new); // 0 on first block

        float psum = 0.0f;
#pragma unroll
        for (int kk = 0; kk < 16; kk++) {
            const float p = __expf(s[kk] - m_new);
            Ps[r * LDP + 4 * kk + seg] = p;
            psum += p;
        }
        psum += __shfl_xor_sync(0xffffffffu, psum, 1);
        psum += __shfl_xor_sync(0xffffffffu, psum, 2);
        l_i = l_i * corr + psum;
        m_i = m_new;
#pragma unroll
        for (int i = 0; i < 16; i++) acc[i] *= corr;
        __syncwarp();  // P row shared only within the quad (same warp)

        // O += P @ V (thread owns cols 4*i + seg)
#pragma unroll 4
        for (int kl = 0; kl < 64; kl++) {
            const float p = Ps[r * LDP + kl];
            const float* vrow = Vs + kl * LDP + seg;
#pragma unroll
            for (int i = 0; i < 16; i++)
                acc[i] += p * vrow[4 * i];
        }
    }

    // normalize + write out [B, NH, T, HS]
    const float inv = 1.0f / l_i;
    float* op = out + base + (size_t)qg * HS_;
#pragma unroll
    for (int i = 0; i < 16; i++)
        op[4 * i + seg] = acc[i] * inv;
}

// ---------------------------------------------------------------------------
extern "C" void kernel_launch(void* const* d_in, const int* in_sizes, int n_in,
                              void* d_out, int out_size)
{
    (void)in_sizes; (void)n_in; (void)out_size;
    const float* x    = (const float*)d_in[0];
    const float* w    = (const float*)d_in[1];
    const float* bias = (const float*)d_in[2];
    float* out = (float*)d_out;

    dim3 g1(N3_ / 128, M_ / 128);   // (18, 32)
    qkv_gemm_kernel<<<g1, 256>>>(x, w, bias);

    cudaFuncSetAttribute(attn_kernel,
                         cudaFuncAttributeMaxDynamicSharedMemorySize,
                         ATTN_SMEM);
    dim3 g2(T_ / 64, NH_, B_);      // (32, 12, 2)
    attn_kernel<<<g2, 256, ATTN_SMEM>>>(out);
}

// round 4
// speedup vs baseline: 3.1329x; 3.1329x over previous
#include <cuda_runtime.h>
#include <math.h>

// Problem constants
constexpr int B_  = 2;
constexpr int T_  = 2048;
constexpr int C_  = 768;
constexpr int NH_ = 12;
constexpr int HS_ = 64;
constexpr int M_  = B_ * T_;      // 4096
constexpr int N3_ = 3 * C_;       // 2304
constexpr int K_  = C_;           // 768

typedef unsigned long long ull;

// Packed fp32x2 helpers (sm_103a FFMA2 — only reachable via PTX)
__device__ __forceinline__ ull dup2(float x) {
    ull r; asm("mov.b64 %0, {%1, %1};" : "=l"(r) : "f"(x)); return r;
}
__device__ __forceinline__ void fma2(ull& d, ull a, ull b) {
    asm("fma.rn.f32x2 %0, %1, %2, %0;" : "+l"(d) : "l"(a), "l"(b));
}
__device__ __forceinline__ void mul2(ull& d, ull a, ull b) {
    asm("mul.rn.f32x2 %0, %1, %2;" : "=l"(d) : "l"(a), "l"(b));
}
__device__ __forceinline__ float2 unpk(ull v) {
    float2 f; asm("mov.b64 {%0, %1}, %2;" : "=f"(f.x), "=f"(f.y) : "l"(v));
    return f;
}

// Scratch Q/K/V in [B, NH, T, HS] layout
__device__ float g_q[(size_t)B_ * NH_ * T_ * HS_];
__device__ float g_k[(size_t)B_ * NH_ * T_ * HS_];
__device__ float g_v[(size_t)B_ * NH_ * T_ * HS_];

// ---------------------------------------------------------------------------
// Kernel 1: qkv = x @ w + b with f32x2 packed inner loop.
// 128x128 tile, BK=8, 256 threads, 8x8 register blocking.
// Thread (ty,tx): rows ty*8..+7, cols {4tx..+3} U {64+4tx..+3}.
// ---------------------------------------------------------------------------
__global__ __launch_bounds__(256) void qkv_gemm_kernel(
    const float* __restrict__ x,      // [M_, K_]
    const float* __restrict__ w,      // [K_, N3_]
    const float* __restrict__ bias)   // [N3_]
{
    __shared__ float As[8][128];      // As[k][m]
    __shared__ float Bs[8][128];      // Bs[k][n]

    const int tid = threadIdx.x;
    const int m0 = blockIdx.y * 128;
    const int n0 = blockIdx.x * 128;
    const int ty = tid / 16;
    const int tx = tid % 16;

    const int arow = tid >> 1;
    const int acol = (tid & 1) * 4;
    const int brow = tid >> 5;
    const int bcol = (tid & 31) * 4;

    ull acc[8][4];
#pragma unroll
    for (int i = 0; i < 8; i++)
#pragma unroll
        for (int p = 0; p < 4; p++) acc[i][p] = 0ULL;

    for (int k0 = 0; k0 < K_; k0 += 8) {
        float4 av = *reinterpret_cast<const float4*>(
            &x[(size_t)(m0 + arow) * K_ + k0 + acol]);
        As[acol + 0][arow] = av.x;
        As[acol + 1][arow] = av.y;
        As[acol + 2][arow] = av.z;
        As[acol + 3][arow] = av.w;
        *reinterpret_cast<float4*>(&Bs[brow][bcol]) =
            *reinterpret_cast<const float4*>(&w[(size_t)(k0 + brow) * N3_ + n0 + bcol]);
        __syncthreads();

#pragma unroll
        for (int k = 0; k < 8; k++) {
            float af[8];
            *reinterpret_cast<float4*>(&af[0]) =
                *reinterpret_cast<const float4*>(&As[k][ty * 8]);
            *reinterpret_cast<float4*>(&af[4]) =
                *reinterpret_cast<const float4*>(&As[k][ty * 8 + 4]);
            ulonglong2 bA = *reinterpret_cast<const ulonglong2*>(&Bs[k][4 * tx]);
            ulonglong2 bB = *reinterpret_cast<const ulonglong2*>(&Bs[k][64 + 4 * tx]);
#pragma unroll
            for (int i = 0; i < 8; i++) {
                ull aa = dup2(af[i]);
                fma2(acc[i][0], aa, bA.x);
                fma2(acc[i][1], aa, bA.y);
                fma2(acc[i][2], aa, bB.x);
                fma2(acc[i][3], aa, bB.y);
            }
        }
        __syncthreads();
    }

    // Epilogue: bias + scatter to [B, NH, T, HS]
#pragma unroll
    for (int i = 0; i < 8; i++) {
        const int m = m0 + ty * 8 + i;
        const int bb = m / T_;
        const int t  = m % T_;
#pragma unroll
        for (int p = 0; p < 4; p++) {
            const int c0 = (p < 2) ? (4 * tx + 2 * p) : (64 + 4 * tx + 2 * (p - 2));
            float2 f = unpk(acc[i][p]);
            float vv[2] = {f.x, f.y};
#pragma unroll
            for (int half = 0; half < 2; half++) {
                const int n = n0 + c0 + half;
                const float val = vv[half] + bias[n];
                const int which = n / C_;
                const int wn    = n - which * C_;
                const int head  = wn / HS_;
                const int d     = wn % HS_;
                float* dst = (which == 0) ? g_q : (which == 1) ? g_k : g_v;
                dst[(((size_t)bb * NH_ + head) * T_ + t) * HS_ + d] = val;
            }
        }
    }
}

// ---------------------------------------------------------------------------
// Kernel 2: flash-style causal attention, register-blocked 4x4 + f32x2.
// CTA per (b, h, 64-row q-tile). 256 threads = 16x16 grid of threads:
// thread (ty,tx) owns S/O rows 4ty..+3 and cols 4tx..+3.
// ---------------------------------------------------------------------------
constexpr int LD = 68;                                        // padded stride
constexpr int ATTN_SMEM = 4 * 64 * LD * (int)sizeof(float);   // 69632 B

__global__ __launch_bounds__(256, 2) void attn_kernel(float* __restrict__ out)
{
    extern __shared__ float sm[];
    float* Qs = sm;              // [row][d]   row-major
    float* Kt = Qs + 64 * LD;    // [d][key]   transposed
    float* Vs = Kt + 64 * LD;    // [key][d]   row-major
    float* Ps = Vs + 64 * LD;    // [row][key] row-major

    const int tid = threadIdx.x;
    const int qt  = (T_ / 64) - 1 - blockIdx.x;   // heavy tiles first
    const int h   = blockIdx.y;
    const int b   = blockIdx.z;
    const size_t base = ((size_t)b * NH_ + h) * T_ * HS_;

    const int ty = tid >> 4, tx = tid & 15;
    const int row4 = ty * 4, col4 = tx * 4;

    // cooperative Q tile load (row-major)
    {
        const int r  = tid >> 2;
        const int cp = (tid & 3) * 16;
        const float* src = g_q + base + (size_t)(qt * 64 + r) * HS_ + cp;
        float* dst = Qs + r * LD + cp;
#pragma unroll
        for (int i = 0; i < 4; i++)
            reinterpret_cast<float4*>(dst)[i] =
                reinterpret_cast<const float4*>(src)[i];
    }

    float m_i[4], l_i[4];
    ull acc[4][2];
#pragma unroll
    for (int i = 0; i < 4; i++) {
        m_i[i] = -INFINITY; l_i[i] = 0.0f;
        acc[i][0] = 0ULL; acc[i][1] = 0ULL;
    }
    const float scale = 0.125f;

    for (int j = 0; j <= qt; j++) {
        __syncthreads();
        // load K (transposed) and V (row-major)
        {
            const int r  = tid >> 2;
            const int cp = (tid & 3) * 16;
            const float* ksrc = g_k + base + (size_t)(j * 64 + r) * HS_ + cp;
            const float* vsrc = g_v + base + (size_t)(j * 64 + r) * HS_ + cp;
            float ka[16];
#pragma unroll
            for (int i = 0; i < 4; i++) {
                *reinterpret_cast<float4*>(&ka[4 * i]) =
                    reinterpret_cast<const float4*>(ksrc)[i];
                reinterpret_cast<float4*>(Vs + r * LD + cp)[i] =
                    reinterpret_cast<const float4*>(vsrc)[i];
            }
#pragma unroll
            for (int c = 0; c < 16; c++)
                Kt[(cp + c) * LD + r] = ka[c];
        }
        __syncthreads();

        // ---- S = Q K^T (4x4 register tile, packed f32x2) ----
        ull sp[4][2];
#pragma unroll
        for (int i = 0; i < 4; i++) { sp[i][0] = 0ULL; sp[i][1] = 0ULL; }

#pragma unroll 4
        for (int d0 = 0; d0 < 64; d0 += 4) {
            float aq[4][4];
#pragma unroll
            for (int i = 0; i < 4; i++)
                *reinterpret_cast<float4*>(aq[i]) =
                    *reinterpret_cast<const float4*>(Qs + (row4 + i) * LD + d0);
#pragma unroll
            for (int u = 0; u < 4; u++) {
                ulonglong2 kb = *reinterpret_cast<const ulonglong2*>(
                    Kt + (d0 + u) * LD + col4);
#pragma unroll
                for (int i = 0; i < 4; i++) {
                    ull aa = dup2(aq[i][u]);
                    fma2(sp[i][0], aa, kb.x);
                    fma2(sp[i][1], aa, kb.y);
                }
            }
        }

        float s[4][4];
#pragma unroll
        for (int i = 0; i < 4; i++) {
            float2 f0 = unpk(sp[i][0]), f1 = unpk(sp[i][1]);
            s[i][0] = f0.x * scale; s[i][1] = f0.y * scale;
            s[i][2] = f1.x * scale; s[i][3] = f1.y * scale;
        }

        if (j == qt) {   // diagonal block: causal mask
#pragma unroll
            for (int i = 0; i < 4; i++)
#pragma unroll
                for (int jj = 0; jj < 4; jj++)
                    if (col4 + jj > row4 + i) s[i][jj] = -INFINITY;
        }

        // ---- online softmax (row stats replicated across tx group) ----
#pragma unroll
        for (int i = 0; i < 4; i++) {
            float mx = fmaxf(fmaxf(s[i][0], s[i][1]), fmaxf(s[i][2], s[i][3]));
            mx = fmaxf(mx, __shfl_xor_sync(0xffffffffu, mx, 1));
            mx = fmaxf(mx, __shfl_xor_sync(0xffffffffu, mx, 2));
            mx = fmaxf(mx, __shfl_xor_sync(0xffffffffu, mx, 4));
            mx = fmaxf(mx, __shfl_xor_sync(0xffffffffu, mx, 8));
            const float mn   = fmaxf(m_i[i], mx);
            const float corr = __expf(m_i[i] - mn);
            m_i[i] = mn;
            float sum = 0.0f;
#pragma unroll
            for (int jj = 0; jj < 4; jj++) {
                const float p = __expf(s[i][jj] - mn);
                s[i][jj] = p;
                sum += p;
            }
            sum += __shfl_xor_sync(0xffffffffu, sum, 1);
            sum += __shfl_xor_sync(0xffffffffu, sum, 2);
            sum += __shfl_xor_sync(0xffffffffu, sum, 4);
            sum += __shfl_xor_sync(0xffffffffu, sum, 8);
            l_i[i] = l_i[i] * corr + sum;
            ull cc = dup2(corr);
            mul2(acc[i][0], acc[i][0], cc);
            mul2(acc[i][1], acc[i][1], cc);
            *reinterpret_cast<float4*>(Ps + (row4 + i) * LD + col4) =
                make_float4(s[i][0], s[i][1], s[i][2], s[i][3]);
        }
        __syncthreads();

        // ---- O += P V (4x4 register tile, packed f32x2) ----
#pragma unroll 4
        for (int kl0 = 0; kl0 < 64; kl0 += 4) {
            float pa[4][4];
#pragma unroll
            for (int i = 0; i < 4; i++)
                *reinterpret_cast<float4*>(pa[i]) =
                    *reinterpret_cast<const float4*>(Ps + (row4 + i) * LD + kl0);
#pragma unroll
            for (int u = 0; u < 4; u++) {
                ulonglong2 vb = *reinterpret_cast<const ulonglong2*>(
                    Vs + (kl0 + u) * LD + col4);
#pragma unroll
                for (int i = 0; i < 4; i++) {
                    ull aa = dup2(pa[i][u]);
                    fma2(acc[i][0], aa, vb.x);
                    fma2(acc[i][1], aa, vb.y);
                }
            }
        }
    }

    // ---- normalize + write [B, NH, T, HS] ----
#pragma unroll
    for (int i = 0; i < 4; i++) {
        const float inv = 1.0f / l_i[i];
        float2 f0 = unpk(acc[i][0]), f1 = unpk(acc[i][1]);
        float4 o = make_float4(f0.x * inv, f0.y * inv, f1.x * inv, f1.y * inv);
        *reinterpret_cast<float4*>(
            out + base + (size_t)(qt * 64 + row4 + i) * HS_ + col4) = o;
    }
}

// ---------------------------------------------------------------------------
extern "C" void kernel_launch(void* const* d_in, const int* in_sizes, int n_in,
                              void* d_out, int out_size)
{
    (void)in_sizes; (void)n_in; (void)out_size;
    const float* x    = (const float*)d_in[0];
    const float* w    = (const float*)d_in[1];
    const float* bias = (const float*)d_in[2];
    float* out = (float*)d_out;

    dim3 g1(N3_ / 128, M_ / 128);   // (18, 32)
    qkv_gemm_kernel<<<g1, 256>>>(x, w, bias);

    cudaFuncSetAttribute(attn_kernel,
                         cudaFuncAttributeMaxDynamicSharedMemorySize,
                         ATTN_SMEM);
    dim3 g2(T_ / 64, NH_, B_);      // (32, 12, 2)
    attn_kernel<<<g2, 256, ATTN_SMEM>>>(out);
}

// round 5
// speedup vs baseline: 3.4598x; 1.1043x over previous
#include <cuda_runtime.h>
#include <math.h>

// Problem constants
constexpr int B_  = 2;
constexpr int T_  = 2048;
constexpr int C_  = 768;
constexpr int NH_ = 12;
constexpr int HS_ = 64;
constexpr int M_  = B_ * T_;      // 4096
constexpr int N3_ = 3 * C_;       // 2304
constexpr int K_  = C_;           // 768

typedef unsigned long long ull;

// Packed fp32x2 helpers (sm_103a FFMA2 — only reachable via PTX)
__device__ __forceinline__ ull dup2(float x) {
    ull r; asm("mov.b64 %0, {%1, %1};" : "=l"(r) : "f"(x)); return r;
}
__device__ __forceinline__ void fma2(ull& d, ull a, ull b) {
    asm("fma.rn.f32x2 %0, %1, %2, %0;" : "+l"(d) : "l"(a), "l"(b));
}
__device__ __forceinline__ void mul2(ull& d, ull a, ull b) {
    asm("mul.rn.f32x2 %0, %1, %2;" : "=l"(d) : "l"(a), "l"(b));
}
__device__ __forceinline__ float2 unpk(ull v) {
    float2 f; asm("mov.b64 {%0, %1}, %2;" : "=f"(f.x), "=f"(f.y) : "l"(v));
    return f;
}

// Scratch Q/K/V in [B, NH, T, HS] layout
__device__ float g_q[(size_t)B_ * NH_ * T_ * HS_];
__device__ float g_k[(size_t)B_ * NH_ * T_ * HS_];
__device__ float g_v[(size_t)B_ * NH_ * T_ * HS_];

// ---------------------------------------------------------------------------
// Kernel 1: qkv = x @ w + b, f32x2 inner loop, double-buffered smem.
// 128x128 tile, BK=8, 256 threads, 8x8 register blocking.
// ---------------------------------------------------------------------------
__global__ __launch_bounds__(256) void qkv_gemm_kernel(
    const float* __restrict__ x,      // [M_, K_]
    const float* __restrict__ w,      // [K_, N3_]
    const float* __restrict__ bias)   // [N3_]
{
    __shared__ float As[2][8][128];   // As[buf][k][m]
    __shared__ float Bs[2][8][128];   // Bs[buf][k][n]

    const int tid = threadIdx.x;
    const int m0 = blockIdx.y * 128;
    const int n0 = blockIdx.x * 128;
    const int ty = tid / 16;
    const int tx = tid % 16;

    const int arow = tid >> 1;
    const int acol = (tid & 1) * 4;
    const int brow = tid >> 5;
    const int bcol = (tid & 31) * 4;

    ull acc[8][4];
#pragma unroll
    for (int i = 0; i < 8; i++)
#pragma unroll
        for (int p = 0; p < 4; p++) acc[i][p] = 0ULL;

    // prologue: tile 0 -> buf 0
    {
        float4 av = *reinterpret_cast<const float4*>(
            &x[(size_t)(m0 + arow) * K_ + acol]);
        As[0][acol + 0][arow] = av.x;
        As[0][acol + 1][arow] = av.y;
        As[0][acol + 2][arow] = av.z;
        As[0][acol + 3][arow] = av.w;
        *reinterpret_cast<float4*>(&Bs[0][brow][bcol]) =
            *reinterpret_cast<const float4*>(&w[(size_t)brow * N3_ + n0 + bcol]);
    }
    __syncthreads();

    int buf = 0;
    for (int k0 = 0; k0 < K_; k0 += 8) {
        const bool has_next = (k0 + 8 < K_);
        float4 av2, bv2;
        if (has_next) {
            av2 = *reinterpret_cast<const float4*>(
                &x[(size_t)(m0 + arow) * K_ + k0 + 8 + acol]);
            bv2 = *reinterpret_cast<const float4*>(
                &w[(size_t)(k0 + 8 + brow) * N3_ + n0 + bcol]);
        }

#pragma unroll
        for (int k = 0; k < 8; k++) {
            float af[8];
            *reinterpret_cast<float4*>(&af[0]) =
                *reinterpret_cast<const float4*>(&As[buf][k][ty * 8]);
            *reinterpret_cast<float4*>(&af[4]) =
                *reinterpret_cast<const float4*>(&As[buf][k][ty * 8 + 4]);
            ulonglong2 bA = *reinterpret_cast<const ulonglong2*>(&Bs[buf][k][4 * tx]);
            ulonglong2 bB = *reinterpret_cast<const ulonglong2*>(&Bs[buf][k][64 + 4 * tx]);
#pragma unroll
            for (int i = 0; i < 8; i++) {
                ull aa = dup2(af[i]);
                fma2(acc[i][0], aa, bA.x);
                fma2(acc[i][1], aa, bA.y);
                fma2(acc[i][2], aa, bB.x);
                fma2(acc[i][3], aa, bB.y);
            }
        }

        if (has_next) {
            const int nb = buf ^ 1;
            As[nb][acol + 0][arow] = av2.x;
            As[nb][acol + 1][arow] = av2.y;
            As[nb][acol + 2][arow] = av2.z;
            As[nb][acol + 3][arow] = av2.w;
            *reinterpret_cast<float4*>(&Bs[nb][brow][bcol]) = bv2;
            __syncthreads();
        }
        buf ^= 1;
    }

    // Epilogue: bias + scatter to [B, NH, T, HS]
#pragma unroll
    for (int i = 0; i < 8; i++) {
        const int m = m0 + ty * 8 + i;
        const int bb = m / T_;
        const int t  = m % T_;
#pragma unroll
        for (int p = 0; p < 4; p++) {
            const int c0 = (p < 2) ? (4 * tx + 2 * p) : (64 + 4 * tx + 2 * (p - 2));
            float2 f = unpk(acc[i][p]);
            float vv[2] = {f.x, f.y};
#pragma unroll
            for (int half = 0; half < 2; half++) {
                const int n = n0 + c0 + half;
                const float val = vv[half] + bias[n];
                const int which = n / C_;
                const int wn    = n - which * C_;
                const int head  = wn / HS_;
                const int d     = wn % HS_;
                float* dst = (which == 0) ? g_q : (which == 1) ? g_k : g_v;
                dst[(((size_t)bb * NH_ + head) * T_ + t) * HS_ + d] = val;
            }
        }
    }
}

// ---------------------------------------------------------------------------
// Kernel 2: flash-style causal attention, BR=128 q-rows, BC=64 keys,
// 8x4 register tile per thread + f32x2.
// 256 threads: ty=tid/16 (rows 8ty..+7), tx=tid%16 (cols 4tx..+3).
// All 16 tx lanes of a row group live in the same warp -> Q/P row loads are
// warp broadcasts and the P-staging barrier is just __syncwarp.
// ---------------------------------------------------------------------------
constexpr int BR  = 128;
constexpr int BC  = 64;
constexpr int LDA = 68;                                    // padded stride
constexpr int ATTN_SMEM = (BR + BC + BC + BR) * LDA * (int)sizeof(float); // 104448

__global__ __launch_bounds__(256) void attn_kernel(float* __restrict__ out)
{
    extern __shared__ float sm[];
    float* Qs = sm;                   // [row][d]   row-major
    float* Kt = Qs + BR * LDA;        // [d][key]   transposed
    float* Vs = Kt + BC * LDA;        // [key][d]   row-major
    float* Ps = Vs + BC * LDA;        // [row][key] row-major

    const int tid = threadIdx.x;
    const int qt  = (T_ / BR) - 1 - blockIdx.x;   // heavy tiles first
    const int h   = blockIdx.y;
    const int b   = blockIdx.z;
    const size_t base = ((size_t)b * NH_ + h) * T_ * HS_;

    const int ty = tid >> 4, tx = tid & 15;
    const int row8 = ty * 8, col4 = tx * 4;

    // cooperative Q tile load: 128 rows x 64, 32 floats per thread
    {
        const int r  = tid >> 1;
        const int cp = (tid & 1) * 32;
        const float* src = g_q + base + (size_t)(qt * BR + r) * HS_ + cp;
        float* dst = Qs + r * LDA + cp;
#pragma unroll
        for (int i = 0; i < 8; i++)
            reinterpret_cast<float4*>(dst)[i] =
                reinterpret_cast<const float4*>(src)[i];
    }

    float m_i[8], l_i[8];
    ull acc[8][2];
#pragma unroll
    for (int i = 0; i < 8; i++) {
        m_i[i] = -INFINITY; l_i[i] = 0.0f;
        acc[i][0] = 0ULL; acc[i][1] = 0ULL;
    }
    const float scale = 0.125f;

    const int jmax = 2 * qt + 1;
    for (int j = 0; j <= jmax; j++) {
        __syncthreads();   // everyone done reading previous K/V
        // load K (transposed, bank-conflict-free permuted store) and V
        {
            const int r  = tid >> 2;
            const int cp = (tid & 3) * 16;
            const int ph = tid & 3;
            const float* ksrc = g_k + base + (size_t)(j * BC + r) * HS_ + cp;
            const float* vsrc = g_v + base + (size_t)(j * BC + r) * HS_ + cp;
            float ka[16];
#pragma unroll
            for (int i = 0; i < 4; i++) {
                *reinterpret_cast<float4*>(&ka[4 * i]) =
                    reinterpret_cast<const float4*>(ksrc)[i];
                reinterpret_cast<float4*>(Vs + r * LDA + cp)[i] =
                    reinterpret_cast<const float4*>(vsrc)[i];
            }
#pragma unroll
            for (int c = 0; c < 16; c++) {
                const int c2 = (c + ph) & 15;     // break 4-way bank conflict
                Kt[(cp + c2) * LDA + r] = ka[c2];
            }
        }
        __syncthreads();

        // ---- S = Q K^T : 8x4 register tile ----
        ull sp[8][2];
#pragma unroll
        for (int i = 0; i < 8; i++) { sp[i][0] = 0ULL; sp[i][1] = 0ULL; }

#pragma unroll 2
        for (int d0 = 0; d0 < HS_; d0 += 4) {
            ulonglong2 kb[4];
#pragma unroll
            for (int u = 0; u < 4; u++)
                kb[u] = *reinterpret_cast<const ulonglong2*>(
                    Kt + (d0 + u) * LDA + col4);
#pragma unroll
            for (int hlf = 0; hlf < 2; hlf++) {
                float aq[4][4];
#pragma unroll
                for (int i = 0; i < 4; i++)
                    *reinterpret_cast<float4*>(aq[i]) =
                        *reinterpret_cast<const float4*>(
                            Qs + (row8 + hlf * 4 + i) * LDA + d0);
#pragma unroll
                for (int u = 0; u < 4; u++)
#pragma unroll
                    for (int i = 0; i < 4; i++) {
                        ull aa = dup2(aq[i][u]);
                        fma2(sp[hlf * 4 + i][0], aa, kb[u].x);
                        fma2(sp[hlf * 4 + i][1], aa, kb[u].y);
                    }
            }
        }

        float s[8][4];
#pragma unroll
        for (int i = 0; i < 8; i++) {
            float2 f0 = unpk(sp[i][0]), f1 = unpk(sp[i][1]);
            s[i][0] = f0.x * scale; s[i][1] = f0.y * scale;
            s[i][2] = f1.x * scale; s[i][3] = f1.y * scale;
        }

        if (j >= 2 * qt) {                 // diagonal-straddling blocks
            const int koff = j * BC - qt * BR;
#pragma unroll
            for (int i = 0; i < 8; i++)
#pragma unroll
                for (int c = 0; c < 4; c++)
                    if (koff + col4 + c > row8 + i) s[i][c] = -INFINITY;
        }

        // ---- online softmax (row stats across the 16 tx lanes) ----
#pragma unroll
        for (int i = 0; i < 8; i++) {
            float mx = fmaxf(fmaxf(s[i][0], s[i][1]), fmaxf(s[i][2], s[i][3]));
            mx = fmaxf(mx, __shfl_xor_sync(0xffffffffu, mx, 1));
            mx = fmaxf(mx, __shfl_xor_sync(0xffffffffu, mx, 2));
            mx = fmaxf(mx, __shfl_xor_sync(0xffffffffu, mx, 4));
            mx = fmaxf(mx, __shfl_xor_sync(0xffffffffu, mx, 8));
            const float mn   = fmaxf(m_i[i], mx);
            const float corr = __expf(m_i[i] - mn);
            m_i[i] = mn;
            float sum = 0.0f;
#pragma unroll
            for (int c = 0; c < 4; c++) {
                const float p = __expf(s[i][c] - mn);
                s[i][c] = p;
                sum += p;
            }
            sum += __shfl_xor_sync(0xffffffffu, sum, 1);
            sum += __shfl_xor_sync(0xffffffffu, sum, 2);
            sum += __shfl_xor_sync(0xffffffffu, sum, 4);
            sum += __shfl_xor_sync(0xffffffffu, sum, 8);
            l_i[i] = l_i[i] * corr + sum;
            ull cc = dup2(corr);
            mul2(acc[i][0], acc[i][0], cc);
            mul2(acc[i][1], acc[i][1], cc);
            *reinterpret_cast<float4*>(Ps + (row8 + i) * LDA + col4) =
                make_float4(s[i][0], s[i][1], s[i][2], s[i][3]);
        }
        __syncwarp();   // all producers of each P row are in this warp

        // ---- O += P V : 8x4 register tile ----
#pragma unroll 2
        for (int kl0 = 0; kl0 < BC; kl0 += 4) {
            ulonglong2 vb[4];
#pragma unroll
            for (int u = 0; u < 4; u++)
                vb[u] = *reinterpret_cast<const ulonglong2*>(
                    Vs + (kl0 + u) * LDA + col4);
#pragma unroll
            for (int hlf = 0; hlf < 2; hlf++) {
                float pa[4][4];
#pragma unroll
                for (int i = 0; i < 4; i++)
                    *reinterpret_cast<float4*>(pa[i]) =
                        *reinterpret_cast<const float4*>(
                            Ps + (row8 + hlf * 4 + i) * LDA + kl0);
#pragma unroll
                for (int u = 0; u < 4; u++)
#pragma unroll
                    for (int i = 0; i < 4; i++) {
                        ull aa = dup2(pa[i][u]);
                        fma2(acc[hlf * 4 + i][0], aa, vb[u].x);
                        fma2(acc[hlf * 4 + i][1], aa, vb[u].y);
                    }
            }
        }
    }

    // ---- normalize + write [B, NH, T, HS] ----
#pragma unroll
    for (int i = 0; i < 8; i++) {
        const float inv = 1.0f / l_i[i];
        float2 f0 = unpk(acc[i][0]), f1 = unpk(acc[i][1]);
        float4 o = make_float4(f0.x * inv, f0.y * inv, f1.x * inv, f1.y * inv);
        *reinterpret_cast<float4*>(
            out + base + (size_t)(qt * BR + row8 + i) * HS_ + col4) = o;
    }
}

// ---------------------------------------------------------------------------
extern "C" void kernel_launch(void* const* d_in, const int* in_sizes, int n_in,
                              void* d_out, int out_size)
{
    (void)in_sizes; (void)n_in; (void)out_size;
    const float* x    = (const float*)d_in[0];
    const float* w    = (const float*)d_in[1];
    const float* bias = (const float*)d_in[2];
    float* out = (float*)d_out;

    dim3 g1(N3_ / 128, M_ / 128);   // (18, 32)
    qkv_gemm_kernel<<<g1, 256>>>(x, w, bias);

    cudaFuncSetAttribute(attn_kernel,
                         cudaFuncAttributeMaxDynamicSharedMemorySize,
                         ATTN_SMEM);
    dim3 g2(T_ / BR, NH_, B_);      // (16, 12, 2)
    attn_kernel<<<g2, 256, ATTN_SMEM>>>(out);
}